// round 9
// baseline (speedup 1.0000x reference)
#include <cuda_runtime.h>
#include <cstdint>
#include <cstddef>

#define NHEAD 12
#define DH    64
#define HID   768
#define NTOK  1024
#define BH    48
#define MTOK  4096
#define NQKV  2304

// ---------------- scratch (device globals) ----------------
__device__ __align__(256) float g_q   [(size_t)BH * NTOK * DH];
__device__ __align__(256) float g_k   [(size_t)BH * NTOK * DH];
__device__ __align__(256) float g_kT  [(size_t)BH * DH * NTOK];
__device__ __align__(256) float g_v   [(size_t)BH * NTOK * DH];
__device__ __align__(256) float g_relh[(size_t)BH * NTOK * 32];
__device__ __align__(256) float g_relw[(size_t)BH * NTOK * 32];
__device__ __align__(256) float g_attn[(size_t)BH * NTOK * NTOK];
__device__ __align__(256) float g_o   [(size_t)MTOK * HID];

// ---------------- f32x2 packed helpers ----------------
#define FMA2(d, a, b) \
    asm("fma.rn.f32x2 %0, %1, %2, %0;" : "+l"(d) : "l"(a), "l"(b))
#define UNPACK2(x, y, d) do {                                     \
    unsigned _lo, _hi;                                            \
    asm("mov.b64 {%0, %1}, %2;" : "=r"(_lo), "=r"(_hi) : "l"(d)); \
    x = __uint_as_float(_lo); y = __uint_as_float(_hi); } while (0)

__device__ __forceinline__ float4 quad_of(unsigned long long p0,
                                          unsigned long long p1) {
    float4 v;
    UNPACK2(v.x, v.y, p0);
    UNPACK2(v.z, v.w, p1);
    return v;
}

// ================= FFMA2 GEMM core =================
// C(128 x BN) = A(128 x K) * B(K x BN), fp32. A row-major (k contig), B k-rows.
// 256 threads = 8 warps (4m x 2n). Warp tile 32 x (BN/2). Lane grid 4x8.
// Micro-tile 8 rows x (BN/16) cols per thread; accumulators packed as column
// pairs in u64 (FFMA2). A stored DUPLICATED in smem -> (a,a) operands are
// direct LDS.128; B column pairs are natural contiguous u64 -> zero PACK ops.
#define ASD_LD 264                    // 2*128 dup + pad (floats)
#define BS_LD  132                    // 128 + pad (floats)
#define STG_F  (8 * ASD_LD + 8 * BS_LD)   // 3168 floats per stage

template<int BN>
__device__ __forceinline__ void gemm_core(
    const float* __restrict__ A, int lda,
    const float* __restrict__ B, int ldb,
    int K, int m0, int n0, float* sm, unsigned long long acc[8][BN / 32])
{
    constexpr int NP = BN / 32;       // u64 col-pairs per row: 4 or 2
    const int tid  = threadIdx.x;
    const int warp = tid >> 5, lane = tid & 31;
    const int wm = warp >> 1, wn = warp & 1;
    const int r  = lane >> 3, c = lane & 7;
    const int rb = wm * 32 + r * 4;                  // row base
    const int cb = wn * (BN / 2) + c * 4;            // col base (local)

    // global->smem loader mapping
    const int aM = tid >> 1, aK = (tid & 1) << 2;
    const float* pa = A + (size_t)(m0 + aM) * lda + aK;
    int bK, bN; bool bAct;
    if (BN == 128) { bK = tid >> 5; bN = (tid & 31) << 2; bAct = true; }
    else           { bK = tid >> 4; bN = (tid & 15) << 2; bAct = (tid < 128); }
    const float* pb = B + (size_t)bK * ldb + n0 + bN;

    float4 ra  = *(const float4*)pa;
    float4 rbv = bAct ? *(const float4*)pb : make_float4(0.f, 0.f, 0.f, 0.f);

    #pragma unroll
    for (int i = 0; i < 8; ++i)
        #pragma unroll
        for (int p = 0; p < NP; ++p) acc[i][p] = 0ull;

    auto store_stage = [&](float* As_, float* Bs_) {
        As_[(aK + 0) * ASD_LD + 2 * aM] = ra.x;
        As_[(aK + 0) * ASD_LD + 2 * aM + 1] = ra.x;
        As_[(aK + 1) * ASD_LD + 2 * aM] = ra.y;
        As_[(aK + 1) * ASD_LD + 2 * aM + 1] = ra.y;
        As_[(aK + 2) * ASD_LD + 2 * aM] = ra.z;
        As_[(aK + 2) * ASD_LD + 2 * aM + 1] = ra.z;
        As_[(aK + 3) * ASD_LD + 2 * aM] = ra.w;
        As_[(aK + 3) * ASD_LD + 2 * aM + 1] = ra.w;
        if (bAct) *(float4*)&Bs_[bK * BS_LD + bN] = rbv;
    };

    const int nch = K >> 3;
    store_stage(sm, sm + 8 * ASD_LD);
    __syncthreads();

    for (int cc = 0; cc < nch; ++cc) {
        if (cc + 1 < nch) {
            ra = *(const float4*)(pa + (size_t)(cc + 1) * 8);
            if (bAct) rbv = *(const float4*)(pb + (size_t)(cc + 1) * 8 * ldb);
        }
        const float* As_ = sm + (cc & 1) * STG_F;
        const float* Bs_ = As_ + 8 * ASD_LD;

        #pragma unroll
        for (int kk = 0; kk < 8; ++kk) {
            const float* as = As_ + kk * ASD_LD;
            const float* bs = Bs_ + kk * BS_LD;
            ulonglong2 a0 = *(const ulonglong2*)&as[2 * rb];
            ulonglong2 a1 = *(const ulonglong2*)&as[2 * rb + 4];
            ulonglong2 a2 = *(const ulonglong2*)&as[2 * (rb + 16)];
            ulonglong2 a3 = *(const ulonglong2*)&as[2 * (rb + 16) + 4];
            unsigned long long av[8] = {a0.x, a0.y, a1.x, a1.y,
                                        a2.x, a2.y, a3.x, a3.y};
            unsigned long long bv[NP];
            {
                ulonglong2 b0 = *(const ulonglong2*)&bs[cb];
                bv[0] = b0.x; bv[1] = b0.y;
            }
            if (NP == 4) {
                ulonglong2 b1 = *(const ulonglong2*)&bs[cb + 32];
                bv[2] = b1.x; bv[3] = b1.y;
            }
            #pragma unroll
            for (int i = 0; i < 8; ++i)
                #pragma unroll
                for (int p = 0; p < NP; ++p)
                    FMA2(acc[i][p], av[i], bv[p]);
        }

        if (cc + 1 < nch) {
            float* An = sm + ((cc + 1) & 1) * STG_F;
            store_stage(An, An + 8 * ASD_LD);
            __syncthreads();
        }
    }
}

// row(i) within tile:  rb + (i&3) + (i>>2)*16
#define GEOM()                                             \
    const int tid  = threadIdx.x;                          \
    const int warp = tid >> 5, lane = tid & 31;            \
    const int wm = warp >> 1, wn = warp & 1;               \
    const int r  = lane >> 3, c = lane & 7;                \
    const int rb = wm * 32 + r * 4;                        \
    (void)c;

// ---------------- 1) qkv GEMM + scatter ----------------
__global__ __launch_bounds__(256, 2) void k_qkv(
    const float* __restrict__ x, const float* __restrict__ w)
{
    __shared__ float sm[2 * STG_F];
    GEOM();
    const int n0 = blockIdx.x * 128, m0 = blockIdx.y * 128;
    unsigned long long acc[8][4];
    gemm_core<128>(x, HID, w, NQKV, HID, m0, n0, sm, acc);

    const int nb   = n0 + wn * 64;          // both quads in this 64-block
    const int sel  = nb / 768;
    const int head = (nb % 768) >> 6;
    float* dst = (sel == 0) ? g_q : (sel == 1) ? g_k : g_v;

    #pragma unroll
    for (int i = 0; i < 8; ++i) {
        const int m = m0 + rb + (i & 3) + ((i >> 2) << 4);
        const int b = m >> 10, tok = m & 1023;
        float* row = dst + (((size_t)(b * NHEAD + head) * NTOK + tok) << 6);
        #pragma unroll
        for (int q = 0; q < 2; ++q)
            *(float4*)&row[c * 4 + q * 32] = quad_of(acc[i][2 * q], acc[i][2 * q + 1]);
    }
}

// ---------------- 2) transpose K: (bh,tok,d) -> (bh,d,tok) ----------------
__global__ __launch_bounds__(256) void k_transpose()
{
    __shared__ float t[32][33];
    const int bh   = blockIdx.z;
    const int tok0 = blockIdx.x * 32;
    const int d0   = blockIdx.y * 32;
    const int x  = threadIdx.x, y0 = threadIdx.y;
    const float* src = g_k  + ((size_t)bh << 16);
    float*       dst = g_kT + ((size_t)bh << 16);
    #pragma unroll
    for (int yy = 0; yy < 32; yy += 8)
        t[y0 + yy][x] = src[(size_t)(tok0 + y0 + yy) * DH + d0 + x];
    __syncthreads();
    #pragma unroll
    for (int yy = 0; yy < 32; yy += 8)
        dst[(size_t)(d0 + y0 + yy) * NTOK + tok0 + x] = t[x][y0 + yy];
}

// ---------------- 3) rel_h / rel_w tables ----------------
__global__ __launch_bounds__(64) void k_rel(
    const float* __restrict__ rel_pos_h, const float* __restrict__ rel_pos_w)
{
    const int bh  = blockIdx.y;
    const int tok = blockIdx.x;
    __shared__ float qs[64];
    const int t = threadIdx.x;
    qs[t] = g_q[(((size_t)bh << 10) + tok) * DH + t];
    __syncthreads();
    const int qh = tok >> 5, qw = tok & 31;
    const float* rp; float* out; int ridx;
    if (t < 32) {
        rp = rel_pos_h; ridx = qh - t + 31;
        out = &g_relh[(((size_t)bh << 10) + tok) * 32 + t];
    } else {
        int kw = t - 32;
        rp = rel_pos_w; ridx = qw - kw + 31;
        out = &g_relw[(((size_t)bh << 10) + tok) * 32 + kw];
    }
    const float* rr = rp + (size_t)ridx * DH;
    float s = 0.f;
    #pragma unroll
    for (int cc = 0; cc < 64; ++cc) s = fmaf(qs[cc], rr[cc], s);
    *out = s;
}

// ---------------- 4) logits = scale*Q@K^T + rel_h + rel_w ----------------
__global__ __launch_bounds__(256, 2) void k_logits()
{
    __shared__ float sm[2 * STG_F];
    GEOM();
    const int bh = blockIdx.z;
    const int n0 = blockIdx.x * 128, m0 = blockIdx.y * 128;
    unsigned long long acc[8][4];
    gemm_core<128>(g_q  + ((size_t)bh << 16), DH,
                   g_kT + ((size_t)bh << 16), NTOK,
                   DH, m0, n0, sm, acc);

    const int cbl = wn * 64 + c * 4;
    float* outb = g_attn + ((size_t)bh << 20);

    #pragma unroll
    for (int i = 0; i < 8; ++i) {
        const int tok = m0 + rb + (i & 3) + ((i >> 2) << 4);
        const float* rh = g_relh + (((size_t)bh << 10) + tok) * 32;
        const float* rw = g_relw + (((size_t)bh << 10) + tok) * 32;
        #pragma unroll
        for (int q = 0; q < 2; ++q) {
            const int n = n0 + cbl + q * 32;
            const float bias = rh[n >> 5];
            float4 w4 = *(const float4*)&rw[n & 31];
            float4 v = quad_of(acc[i][2 * q], acc[i][2 * q + 1]);
            float4 o;
            o.x = fmaf(v.x, 0.125f, bias + w4.x);
            o.y = fmaf(v.y, 0.125f, bias + w4.y);
            o.z = fmaf(v.z, 0.125f, bias + w4.z);
            o.w = fmaf(v.w, 0.125f, bias + w4.w);
            *(float4*)&outb[((size_t)tok << 10) + n] = o;
        }
    }
}

// ---------------- 5) softmax (in-place fp32) ----------------
__global__ __launch_bounds__(256) void k_softmax()
{
    const size_t row = blockIdx.x;
    float* p = g_attn + (row << 10);
    const int t = threadIdx.x;
    float4 v = *(const float4*)(p + (t << 2));

    float m = fmaxf(fmaxf(v.x, v.y), fmaxf(v.z, v.w));
    #pragma unroll
    for (int o = 16; o > 0; o >>= 1)
        m = fmaxf(m, __shfl_xor_sync(0xffffffffu, m, o));
    __shared__ float smax[8], ssum[8];
    const int w = t >> 5, lane = t & 31;
    if (lane == 0) smax[w] = m;
    __syncthreads();
    float M = smax[0];
    #pragma unroll
    for (int k = 1; k < 8; ++k) M = fmaxf(M, smax[k]);

    float e0 = __expf(v.x - M), e1 = __expf(v.y - M);
    float e2 = __expf(v.z - M), e3 = __expf(v.w - M);
    float s = e0 + e1 + e2 + e3;
    #pragma unroll
    for (int o = 16; o > 0; o >>= 1)
        s += __shfl_xor_sync(0xffffffffu, s, o);
    if (lane == 0) ssum[w] = s;
    __syncthreads();
    float S = ssum[0];
    #pragma unroll
    for (int k = 1; k < 8; ++k) S += ssum[k];
    const float inv = 1.0f / S;

    *(float4*)(p + (t << 2)) =
        make_float4(e0 * inv, e1 * inv, e2 * inv, e3 * inv);
}

// ---------------- 6) out = P @ V -> g_o ----------------
__global__ __launch_bounds__(256, 2) void k_pv()
{
    __shared__ float sm[2 * STG_F];
    GEOM();
    const int bh = blockIdx.y;
    const int m0 = blockIdx.x * 128;
    unsigned long long acc[8][2];
    gemm_core<64>(g_attn + ((size_t)bh << 20), NTOK,
                  g_v    + ((size_t)bh << 16), DH,
                  NTOK, m0, 0, sm, acc);

    const int head = bh % NHEAD, b = bh / NHEAD;
    const int d0 = wn * 32 + c * 4;

    #pragma unroll
    for (int i = 0; i < 8; ++i) {
        const int tok = m0 + rb + (i & 3) + ((i >> 2) << 4);
        *(float4*)&g_o[(size_t)(b * NTOK + tok) * HID + head * DH + d0] =
            quad_of(acc[i][0], acc[i][1]);
    }
}

// ---------------- 7) final projection ----------------
__global__ __launch_bounds__(256, 2) void k_out(
    const float* __restrict__ w, const float* __restrict__ bias,
    float* __restrict__ out)
{
    __shared__ float sm[2 * STG_F];
    GEOM();
    const int n0 = blockIdx.x * 128, m0 = blockIdx.y * 128;
    unsigned long long acc[8][4];
    gemm_core<128>(g_o, HID, w, HID, HID, m0, n0, sm, acc);

    const int cbl = wn * 64 + c * 4;
    #pragma unroll
    for (int i = 0; i < 8; ++i) {
        const int m = m0 + rb + (i & 3) + ((i >> 2) << 4);
        #pragma unroll
        for (int q = 0; q < 2; ++q) {
            const int col = n0 + cbl + q * 32;
            float4 bb = *(const float4*)&bias[col];
            float4 v = quad_of(acc[i][2 * q], acc[i][2 * q + 1]);
            *(float4*)&out[(size_t)m * HID + col] =
                make_float4(v.x + bb.x, v.y + bb.y, v.z + bb.z, v.w + bb.w);
        }
    }
}

// ---------------- launcher ----------------
extern "C" void kernel_launch(void* const* d_in, const int* in_sizes, int n_in,
                              void* d_out, int out_size)
{
    const float* x         = (const float*)d_in[0];
    const float* w_qkv     = (const float*)d_in[1];
    const float* w_out     = (const float*)d_in[2];
    const float* b_out     = (const float*)d_in[3];
    const float* rel_pos_h = (const float*)d_in[4];
    const float* rel_pos_w = (const float*)d_in[5];
    float* out = (float*)d_out;

    k_qkv<<<dim3(NQKV / 128, MTOK / 128), 256>>>(x, w_qkv);
    k_transpose<<<dim3(32, 2, BH), dim3(32, 8)>>>();
    k_rel<<<dim3(NTOK, BH), 64>>>(rel_pos_h, rel_pos_w);
    k_logits<<<dim3(8, 8, BH), 256>>>();
    k_softmax<<<BH * NTOK, 256>>>();
    k_pv<<<dim3(8, BH), 256>>>();
    k_out<<<dim3(6, 32), 256>>>(w_out, b_out, out);
}

// round 11
// speedup vs baseline: 1.0840x; 1.0840x over previous
#include <cuda_runtime.h>
#include <cstdint>
#include <cstddef>

// Problem constants
#define BATCH   4
#define NHEAD   12
#define DH      64
#define HID     768
#define HDIM    32
#define WDIM    32
#define NTOK    1024
#define BH      48
#define MTOK    4096

#define BM 128
#define BN 64
#define BK 16

// ---------------- scratch (device globals) ----------------
__device__ float g_q   [(size_t)BH * NTOK * DH];
__device__ float g_k   [(size_t)BH * NTOK * DH];
__device__ float g_kT  [(size_t)BH * DH * NTOK];
__device__ float g_v   [(size_t)BH * NTOK * DH];
__device__ float g_relh[(size_t)BH * NTOK * 32];
__device__ float g_relw[(size_t)BH * NTOK * 32];
__device__ float g_attn[(size_t)BH * NTOK * NTOK];
__device__ float g_o   [(size_t)MTOK * HID];

// ---------------- f32x2 packed helpers ----------------
#define FMA2(d, a, b) \
    asm("fma.rn.f32x2 %0, %1, %2, %0;" : "+l"(d) : "l"(a), "l"(b))
#define PACK2(d, x, y) \
    asm("mov.b64 %0, {%1, %2};" : "=l"(d) : "r"(__float_as_uint(x)), "r"(__float_as_uint(y)))
#define UNPACK2(x, y, d) do {                                   \
    unsigned _lo, _hi;                                          \
    asm("mov.b64 {%0, %1}, %2;" : "=r"(_lo), "=r"(_hi) : "l"(d)); \
    x = __uint_as_float(_lo); y = __uint_as_float(_hi); } while (0)

// ---------------- 128x64x16 GEMM core, 256 threads, 8x4 micro, FFMA2 ----------
// acc[ip][j] packs rows (2ip, 2ip+1) of the 8-row micro-tile, column j.
__device__ __forceinline__ void gemm128_core(
    const float* __restrict__ A, int lda,
    const float* __restrict__ B, int ldb,
    int K, int m0, int n0, unsigned long long acc[4][4])
{
    __shared__ __align__(16) float As[BK][BM + 4];   // [k][m]
    __shared__ __align__(16) float Bs[BK][BN + 4];   // [k][n]

    const int tid = threadIdx.x;
    const int tx  = tid & 15;            // col group (4 cols)
    const int ty  = tid >> 4;            // row group (8 rows)

    const int ra  = tid >> 1;            // A row 0..127
    const int ka  = (tid & 1) << 3;      // A k-offset 0 or 8
    const int krb = tid >> 4;            // B k-row 0..15
    const int qb  = (tid & 15) << 2;     // B col chunk

    const float* pa = A + (size_t)(m0 + ra) * lda + ka;
    const float* pb = B + (size_t)krb * ldb + n0 + qb;

    float4 va0 = *reinterpret_cast<const float4*>(pa);
    float4 va1 = *reinterpret_cast<const float4*>(pa + 4);
    float4 vb  = *reinterpret_cast<const float4*>(pb);

    for (int k0 = 0; k0 < K; k0 += BK) {
        As[ka + 0][ra] = va0.x; As[ka + 1][ra] = va0.y;
        As[ka + 2][ra] = va0.z; As[ka + 3][ra] = va0.w;
        As[ka + 4][ra] = va1.x; As[ka + 5][ra] = va1.y;
        As[ka + 6][ra] = va1.z; As[ka + 7][ra] = va1.w;
        *reinterpret_cast<float4*>(&Bs[krb][qb]) = vb;
        __syncthreads();

        const int kn = k0 + BK;
        if (kn < K) {
            va0 = *reinterpret_cast<const float4*>(pa + kn);
            va1 = *reinterpret_cast<const float4*>(pa + kn + 4);
            vb  = *reinterpret_cast<const float4*>(pb + (size_t)kn * ldb);
        }

        #pragma unroll
        for (int kk = 0; kk < BK; ++kk) {
            const ulonglong2* ap =
                reinterpret_cast<const ulonglong2*>(&As[kk][ty << 3]);
            ulonglong2 aa = ap[0];
            ulonglong2 ab = ap[1];
            unsigned long long apair[4] = {aa.x, aa.y, ab.x, ab.y};
            float4 b4 = *reinterpret_cast<const float4*>(&Bs[kk][tx << 2]);
            unsigned long long bp[4];
            PACK2(bp[0], b4.x, b4.x);
            PACK2(bp[1], b4.y, b4.y);
            PACK2(bp[2], b4.z, b4.z);
            PACK2(bp[3], b4.w, b4.w);
            #pragma unroll
            for (int ip = 0; ip < 4; ++ip)
                #pragma unroll
                for (int j = 0; j < 4; ++j)
                    FMA2(acc[ip][j], apair[ip], bp[j]);
        }
        __syncthreads();
    }
}

// Variant for PV: A-loader applies exp(a - M[row]) at smem-store time.
__device__ __forceinline__ void gemm128_core_exp(
    const float* __restrict__ A, int lda,
    const float* __restrict__ B, int ldb,
    int K, int m0, const float* __restrict__ sM,
    unsigned long long acc[4][4])
{
    __shared__ __align__(16) float As[BK][BM + 4];
    __shared__ __align__(16) float Bs[BK][BN + 4];

    const int tid = threadIdx.x;
    const int tx  = tid & 15;
    const int ty  = tid >> 4;

    const int ra  = tid >> 1;
    const int ka  = (tid & 1) << 3;
    const int krb = tid >> 4;
    const int qb  = (tid & 15) << 2;

    const float* pa = A + (size_t)(m0 + ra) * lda + ka;
    const float* pb = B + (size_t)krb * ldb + qb;
    const float Mr = sM[ra];

    float4 va0 = *reinterpret_cast<const float4*>(pa);
    float4 va1 = *reinterpret_cast<const float4*>(pa + 4);
    float4 vb  = *reinterpret_cast<const float4*>(pb);

    for (int k0 = 0; k0 < K; k0 += BK) {
        As[ka + 0][ra] = __expf(va0.x - Mr);
        As[ka + 1][ra] = __expf(va0.y - Mr);
        As[ka + 2][ra] = __expf(va0.z - Mr);
        As[ka + 3][ra] = __expf(va0.w - Mr);
        As[ka + 4][ra] = __expf(va1.x - Mr);
        As[ka + 5][ra] = __expf(va1.y - Mr);
        As[ka + 6][ra] = __expf(va1.z - Mr);
        As[ka + 7][ra] = __expf(va1.w - Mr);
        *reinterpret_cast<float4*>(&Bs[krb][qb]) = vb;
        __syncthreads();

        const int kn = k0 + BK;
        if (kn < K) {
            va0 = *reinterpret_cast<const float4*>(pa + kn);
            va1 = *reinterpret_cast<const float4*>(pa + kn + 4);
            vb  = *reinterpret_cast<const float4*>(pb + (size_t)kn * ldb);
        }

        #pragma unroll
        for (int kk = 0; kk < BK; ++kk) {
            const ulonglong2* ap =
                reinterpret_cast<const ulonglong2*>(&As[kk][ty << 3]);
            ulonglong2 aa = ap[0];
            ulonglong2 ab = ap[1];
            unsigned long long apair[4] = {aa.x, aa.y, ab.x, ab.y};
            float4 b4 = *reinterpret_cast<const float4*>(&Bs[kk][tx << 2]);
            unsigned long long bp[4];
            PACK2(bp[0], b4.x, b4.x);
            PACK2(bp[1], b4.y, b4.y);
            PACK2(bp[2], b4.z, b4.z);
            PACK2(bp[3], b4.w, b4.w);
            #pragma unroll
            for (int ip = 0; ip < 4; ++ip)
                #pragma unroll
                for (int j = 0; j < 4; ++j)
                    FMA2(acc[ip][j], apair[ip], bp[j]);
        }
        __syncthreads();
    }
}

// unpack acc[4][4] (packed row pairs) into r[8][4]
__device__ __forceinline__ void unpack_acc(
    const unsigned long long acc[4][4], float r[8][4])
{
    #pragma unroll
    for (int ip = 0; ip < 4; ++ip)
        #pragma unroll
        for (int j = 0; j < 4; ++j)
            UNPACK2(r[2 * ip][j], r[2 * ip + 1][j], acc[ip][j]);
}

// ---------------- 1) qkv = x @ w_qkv, scatter to g_q/g_k/g_v ----------------
__global__ __launch_bounds__(256) void k_gemm_qkv(
    const float* __restrict__ x, const float* __restrict__ w)
{
    const int m0 = blockIdx.y * BM;
    const int n0 = blockIdx.x * BN;
    unsigned long long acc[4][4] = {};
    gemm128_core(x, HID, w, 3 * NHEAD * DH, HID, m0, n0, acc);
    float r[8][4];
    unpack_acc(acc, r);

    const int tx = threadIdx.x & 15;
    const int ty = threadIdx.x >> 4;
    const int sel  = n0 / (NHEAD * DH);
    const int head = (n0 % (NHEAD * DH)) >> 6;
    float* dst = (sel == 0) ? g_q : (sel == 1) ? g_k : g_v;

    #pragma unroll
    for (int rr = 0; rr < 8; ++rr) {
        const int m = m0 + (ty << 3) + rr;
        const int b = m >> 10;
        const int tok = m & 1023;
        float4 v4 = make_float4(r[rr][0], r[rr][1], r[rr][2], r[rr][3]);
        *reinterpret_cast<float4*>(
            &dst[(((size_t)(b * NHEAD + head) * NTOK + tok) << 6) + (tx << 2)]) = v4;
    }
}

// ---------------- 2) transpose K ----------------
__global__ __launch_bounds__(256) void k_transpose()
{
    __shared__ float t[32][33];
    const int bh   = blockIdx.z;
    const int tok0 = blockIdx.x * 32;
    const int d0   = blockIdx.y * 32;
    const int x  = threadIdx.x;
    const int y0 = threadIdx.y;
    const float* src = g_k  + ((size_t)bh << 16);
    float*       dst = g_kT + ((size_t)bh << 16);
    #pragma unroll
    for (int yy = 0; yy < 32; yy += 8)
        t[y0 + yy][x] = src[(size_t)(tok0 + y0 + yy) * DH + d0 + x];
    __syncthreads();
    #pragma unroll
    for (int yy = 0; yy < 32; yy += 8)
        dst[(size_t)(d0 + y0 + yy) * NTOK + tok0 + x] = t[x][y0 + yy];
}

// ---------------- 3) rel_h / rel_w tables ----------------
__global__ __launch_bounds__(64) void k_rel(
    const float* __restrict__ rel_pos_h, const float* __restrict__ rel_pos_w)
{
    const int bh  = blockIdx.y;
    const int tok = blockIdx.x;
    __shared__ float qs[64];
    const int t = threadIdx.x;
    qs[t] = g_q[(((size_t)bh << 10) + tok) * DH + t];
    __syncthreads();

    const int qh = tok >> 5;
    const int qw = tok & 31;
    const float* rp;
    float* out;
    int ridx;
    if (t < 32) {
        rp = rel_pos_h; ridx = qh - t + (HDIM - 1);
        out = &g_relh[(((size_t)bh << 10) + tok) * 32 + t];
    } else {
        const int kw = t - 32;
        rp = rel_pos_w; ridx = qw - kw + (WDIM - 1);
        out = &g_relw[(((size_t)bh << 10) + tok) * 32 + kw];
    }
    const float* rr = rp + (size_t)ridx * DH;
    float s = 0.f;
    #pragma unroll
    for (int c = 0; c < 64; ++c) s = fmaf(qs[c], rr[c], s);
    *out = s;
}

// ---------------- 4) logits = scale*Q@K^T + rel_h + rel_w ----------------
__global__ __launch_bounds__(256) void k_logits()
{
    const int bh = blockIdx.z;
    const int m0 = blockIdx.y * BM;
    const int n0 = blockIdx.x * BN;
    const float* A = g_q  + ((size_t)bh << 16);
    const float* B = g_kT + ((size_t)bh << 16);
    unsigned long long acc[4][4] = {};
    gemm128_core(A, DH, B, NTOK, DH, m0, n0, acc);
    float r[8][4];
    unpack_acc(acc, r);

    const int tx = threadIdx.x & 15;
    const int ty = threadIdx.x >> 4;
    const float scale = 0.125f;
    const int col0 = n0 + (tx << 2);
    const int kh   = col0 >> 5;
    const int kw0  = col0 & 31;
    float* outb = g_attn + ((size_t)bh << 20);

    #pragma unroll
    for (int rr = 0; rr < 8; ++rr) {
        const int tok = m0 + (ty << 3) + rr;
        const float* rh = g_relh + (((size_t)bh << 10) + tok) * 32;
        const float* rw = g_relw + (((size_t)bh << 10) + tok) * 32;
        const float bias = rh[kh];
        float4 v;
        v.x = fmaf(r[rr][0], scale, bias + rw[kw0 + 0]);
        v.y = fmaf(r[rr][1], scale, bias + rw[kw0 + 1]);
        v.z = fmaf(r[rr][2], scale, bias + rw[kw0 + 2]);
        v.w = fmaf(r[rr][3], scale, bias + rw[kw0 + 3]);
        *reinterpret_cast<float4*>(&outb[((size_t)tok << 10) + col0]) = v;
    }
}

// ---------------- 5) fused softmax + PV: out = softmax(attn) @ V -> g_o --------
__global__ __launch_bounds__(256) void k_pv()
{
    __shared__ float sM[128];
    __shared__ float sInvL[128];

    const int bh = blockIdx.y;
    const int m0 = blockIdx.x * BM;
    const int tid = threadIdx.x;
    const int warp = tid >> 5, lane = tid & 31;

    // prepass: each warp computes online (max, sum) for 16 rows
    const float* attnb = g_attn + ((size_t)bh << 20);
    for (int rr = 0; rr < 16; ++rr) {
        const int rloc = warp * 16 + rr;
        const float4* p = (const float4*)(attnb + ((size_t)(m0 + rloc) << 10));
        float m = -3.4e38f, l = 0.f;
        #pragma unroll
        for (int i = 0; i < 8; ++i) {
            float4 v = p[lane + i * 32];
            float mx = fmaxf(fmaxf(v.x, v.y), fmaxf(v.z, v.w));
            if (mx > m) { l *= __expf(m - mx); m = mx; }
            l += __expf(v.x - m) + __expf(v.y - m)
               + __expf(v.z - m) + __expf(v.w - m);
        }
        #pragma unroll
        for (int o = 16; o > 0; o >>= 1) {
            float mo = __shfl_xor_sync(0xffffffffu, m, o);
            float lo = __shfl_xor_sync(0xffffffffu, l, o);
            float M2 = fmaxf(m, mo);
            l = l * __expf(m - M2) + lo * __expf(mo - M2);
            m = M2;
        }
        if (lane == 0) { sM[rloc] = m; sInvL[rloc] = 1.0f / l; }
    }
    __syncthreads();

    unsigned long long acc[4][4] = {};
    gemm128_core_exp(attnb, NTOK,
                     g_v + ((size_t)bh << 16), DH,
                     NTOK, m0, sM, acc);
    float r[8][4];
    unpack_acc(acc, r);

    const int tx = tid & 15;
    const int ty = tid >> 4;
    const int head = bh % NHEAD;
    const int b    = bh / NHEAD;

    #pragma unroll
    for (int rr = 0; rr < 8; ++rr) {
        const int rloc = (ty << 3) + rr;
        const int tok = m0 + rloc;
        const float inv = sInvL[rloc];
        float4 v4 = make_float4(r[rr][0] * inv, r[rr][1] * inv,
                                r[rr][2] * inv, r[rr][3] * inv);
        *reinterpret_cast<float4*>(
            &g_o[(size_t)(b * NTOK + tok) * HID + head * DH + (tx << 2)]) = v4;
    }
}

// ---------------- 6) final projection ----------------
__global__ __launch_bounds__(256) void k_out(
    const float* __restrict__ w, const float* __restrict__ bias,
    float* __restrict__ out)
{
    const int m0 = blockIdx.y * BM;
    const int n0 = blockIdx.x * BN;
    unsigned long long acc[4][4] = {};
    gemm128_core(g_o, HID, w, HID, HID, m0, n0, acc);
    float r[8][4];
    unpack_acc(acc, r);

    const int tx = threadIdx.x & 15;
    const int ty = threadIdx.x >> 4;
    const int col0 = n0 + (tx << 2);
    float4 bb = *reinterpret_cast<const float4*>(&bias[col0]);

    #pragma unroll
    for (int rr = 0; rr < 8; ++rr) {
        const int m = m0 + (ty << 3) + rr;
        float4 v4 = make_float4(r[rr][0] + bb.x, r[rr][1] + bb.y,
                                r[rr][2] + bb.z, r[rr][3] + bb.w);
        *reinterpret_cast<float4*>(&out[(size_t)m * HID + col0]) = v4;
    }
}

// ---------------- launcher ----------------
extern "C" void kernel_launch(void* const* d_in, const int* in_sizes, int n_in,
                              void* d_out, int out_size)
{
    const float* x         = (const float*)d_in[0];
    const float* w_qkv     = (const float*)d_in[1];
    const float* w_out     = (const float*)d_in[2];
    const float* b_out     = (const float*)d_in[3];
    const float* rel_pos_h = (const float*)d_in[4];
    const float* rel_pos_w = (const float*)d_in[5];
    float* out = (float*)d_out;

    k_gemm_qkv<<<dim3(36, 32), 256>>>(x, w_qkv);
    k_transpose<<<dim3(32, 2, BH), dim3(32, 8)>>>();
    k_rel<<<dim3(NTOK, BH), 64>>>(rel_pos_h, rel_pos_w);
    k_logits<<<dim3(16, 8, BH), 256>>>();
    k_pv<<<dim3(8, BH), 256>>>();
    k_out<<<dim3(12, 32), 256>>>(w_out, b_out, out);
}

// round 12
// speedup vs baseline: 1.0941x; 1.0093x over previous
#include <cuda_runtime.h>
#include <cstdint>
#include <cstddef>

// Problem constants
#define BATCH   4
#define NHEAD   12
#define DH      64
#define HID     768
#define HDIM    32
#define WDIM    32
#define NTOK    1024
#define BH      48
#define MTOK    4096

// ---------------- scratch (device globals) ----------------
__device__ float g_q   [(size_t)BH * NTOK * DH];
__device__ float g_k   [(size_t)BH * NTOK * DH];
__device__ float g_kT  [(size_t)BH * DH * NTOK];
__device__ float g_v   [(size_t)BH * NTOK * DH];
__device__ float g_relh[(size_t)BH * NTOK * 32];
__device__ float g_relw[(size_t)BH * NTOK * 32];
__device__ float g_attn[(size_t)BH * NTOK * NTOK];
__device__ float g_o   [(size_t)MTOK * HID];

// ---------------- f32x2 packed helpers ----------------
#define FMA2(d, a, b) \
    asm("fma.rn.f32x2 %0, %1, %2, %0;" : "+l"(d) : "l"(a), "l"(b))
#define PACK2(d, x, y) \
    asm("mov.b64 %0, {%1, %2};" : "=l"(d) : "r"(__float_as_uint(x)), "r"(__float_as_uint(y)))
#define UNPACK2(x, y, d) do {                                   \
    unsigned _lo, _hi;                                          \
    asm("mov.b64 {%0, %1}, %2;" : "=r"(_lo), "=r"(_hi) : "l"(d)); \
    x = __uint_as_float(_lo); y = __uint_as_float(_hi); } while (0)

// ================= 128x128x16 GEMM core, 256 thr, 8x8 micro ==================
// C(128x128) = A(128xK) * B(Kx128). A row-major (k contig), B k-major rows.
// tx = tid&15 -> 8 cols (tx*8..+7); ty = tid>>4 -> 8 rows (ty*8..+7).
// acc[ip][j]: u64 packing rows (2ip, 2ip+1), col tx*8+j.
// Per kk: 2 LDS.128 (A row-pairs) + 2 LDS.128 (B) + 8 PACK + 32 FFMA2
//   -> 1.0 smem-byte/FLOP (fits 128B/cyc/SM at full FFMA2 rate).
__device__ __forceinline__ void gemm_big_core(
    const float* __restrict__ A, int lda,
    const float* __restrict__ B, int ldb,
    int K, int m0, int n0, unsigned long long acc[4][8])
{
    __shared__ __align__(16) float As[16][132];   // [k][m]
    __shared__ __align__(16) float Bs[16][132];   // [k][n]

    const int tid = threadIdx.x;
    const int tx  = tid & 15;
    const int ty  = tid >> 4;

    const int ra  = tid >> 1;            // A row 0..127
    const int ka  = (tid & 1) << 3;      // A k-offset 0 or 8
    const int krb = tid >> 4;            // B k-row 0..15
    const int qb  = (tid & 15) << 3;     // B col chunk (8 floats)

    const float* pa = A + (size_t)(m0 + ra) * lda + ka;
    const float* pb = B + (size_t)krb * ldb + n0 + qb;

    float4 va0 = *reinterpret_cast<const float4*>(pa);
    float4 va1 = *reinterpret_cast<const float4*>(pa + 4);
    float4 vb0 = *reinterpret_cast<const float4*>(pb);
    float4 vb1 = *reinterpret_cast<const float4*>(pb + 4);

    #pragma unroll
    for (int ip = 0; ip < 4; ++ip)
        #pragma unroll
        for (int j = 0; j < 8; ++j) acc[ip][j] = 0ull;

    for (int k0 = 0; k0 < K; k0 += 16) {
        As[ka + 0][ra] = va0.x; As[ka + 1][ra] = va0.y;
        As[ka + 2][ra] = va0.z; As[ka + 3][ra] = va0.w;
        As[ka + 4][ra] = va1.x; As[ka + 5][ra] = va1.y;
        As[ka + 6][ra] = va1.z; As[ka + 7][ra] = va1.w;
        *reinterpret_cast<float4*>(&Bs[krb][qb])     = vb0;
        *reinterpret_cast<float4*>(&Bs[krb][qb + 4]) = vb1;
        __syncthreads();

        const int kn = k0 + 16;
        if (kn < K) {
            va0 = *reinterpret_cast<const float4*>(pa + kn);
            va1 = *reinterpret_cast<const float4*>(pa + kn + 4);
            vb0 = *reinterpret_cast<const float4*>(pb + (size_t)kn * ldb);
            vb1 = *reinterpret_cast<const float4*>(pb + (size_t)kn * ldb + 4);
        }

        #pragma unroll
        for (int kk = 0; kk < 16; ++kk) {
            const ulonglong2* ap =
                reinterpret_cast<const ulonglong2*>(&As[kk][ty << 3]);
            ulonglong2 aa = ap[0];
            ulonglong2 ab = ap[1];
            unsigned long long apair[4] = {aa.x, aa.y, ab.x, ab.y};
            float4 b0 = *reinterpret_cast<const float4*>(&Bs[kk][tx << 3]);
            float4 b1 = *reinterpret_cast<const float4*>(&Bs[kk][(tx << 3) + 4]);
            float bv[8] = {b0.x, b0.y, b0.z, b0.w, b1.x, b1.y, b1.z, b1.w};
            #pragma unroll
            for (int j = 0; j < 8; ++j) {
                unsigned long long bp;
                PACK2(bp, bv[j], bv[j]);
                #pragma unroll
                for (int ip = 0; ip < 4; ++ip)
                    FMA2(acc[ip][j], apair[ip], bp);
            }
        }
        __syncthreads();
    }
}

// unpack acc[4][8] (row pairs) to r[8][8]
__device__ __forceinline__ void unpack_big(
    const unsigned long long acc[4][8], float r[8][8])
{
    #pragma unroll
    for (int ip = 0; ip < 4; ++ip)
        #pragma unroll
        for (int j = 0; j < 8; ++j)
            UNPACK2(r[2 * ip][j], r[2 * ip + 1][j], acc[ip][j]);
}

// ---------------- PV core (BN=64, 8x4 micro) with exp at A-store --------------
__device__ __forceinline__ void gemm_pv_core(
    const float* __restrict__ A, int lda,
    const float* __restrict__ B, int ldb,
    int K, int m0, const float* __restrict__ sM,
    unsigned long long acc[4][4])
{
    __shared__ __align__(16) float As[16][132];
    __shared__ __align__(16) float Bs[16][68];

    const int tid = threadIdx.x;
    const int tx  = tid & 15;
    const int ty  = tid >> 4;

    const int ra  = tid >> 1;
    const int ka  = (tid & 1) << 3;
    const int krb = tid >> 4;
    const int qb  = (tid & 15) << 2;

    const float* pa = A + (size_t)(m0 + ra) * lda + ka;
    const float* pb = B + (size_t)krb * ldb + qb;
    const float Mr = sM[ra];

    float4 va0 = *reinterpret_cast<const float4*>(pa);
    float4 va1 = *reinterpret_cast<const float4*>(pa + 4);
    float4 vb  = *reinterpret_cast<const float4*>(pb);

    for (int k0 = 0; k0 < K; k0 += 16) {
        As[ka + 0][ra] = __expf(va0.x - Mr);
        As[ka + 1][ra] = __expf(va0.y - Mr);
        As[ka + 2][ra] = __expf(va0.z - Mr);
        As[ka + 3][ra] = __expf(va0.w - Mr);
        As[ka + 4][ra] = __expf(va1.x - Mr);
        As[ka + 5][ra] = __expf(va1.y - Mr);
        As[ka + 6][ra] = __expf(va1.z - Mr);
        As[ka + 7][ra] = __expf(va1.w - Mr);
        *reinterpret_cast<float4*>(&Bs[krb][qb]) = vb;
        __syncthreads();

        const int kn = k0 + 16;
        if (kn < K) {
            va0 = *reinterpret_cast<const float4*>(pa + kn);
            va1 = *reinterpret_cast<const float4*>(pa + kn + 4);
            vb  = *reinterpret_cast<const float4*>(pb + (size_t)kn * ldb);
        }

        #pragma unroll
        for (int kk = 0; kk < 16; ++kk) {
            const ulonglong2* ap =
                reinterpret_cast<const ulonglong2*>(&As[kk][ty << 3]);
            ulonglong2 aa = ap[0];
            ulonglong2 ab = ap[1];
            unsigned long long apair[4] = {aa.x, aa.y, ab.x, ab.y};
            float4 b4 = *reinterpret_cast<const float4*>(&Bs[kk][tx << 2]);
            unsigned long long bp[4];
            PACK2(bp[0], b4.x, b4.x);
            PACK2(bp[1], b4.y, b4.y);
            PACK2(bp[2], b4.z, b4.z);
            PACK2(bp[3], b4.w, b4.w);
            #pragma unroll
            for (int ip = 0; ip < 4; ++ip)
                #pragma unroll
                for (int j = 0; j < 4; ++j)
                    FMA2(acc[ip][j], apair[ip], bp[j]);
        }
        __syncthreads();
    }
}

__device__ __forceinline__ void unpack_acc(
    const unsigned long long acc[4][4], float r[8][4])
{
    #pragma unroll
    for (int ip = 0; ip < 4; ++ip)
        #pragma unroll
        for (int j = 0; j < 4; ++j)
            UNPACK2(r[2 * ip][j], r[2 * ip + 1][j], acc[ip][j]);
}

// ---------------- 1) qkv = x @ w_qkv, scatter to g_q/g_k/g_v ----------------
__global__ __launch_bounds__(256) void k_gemm_qkv(
    const float* __restrict__ x, const float* __restrict__ w)
{
    const int m0 = blockIdx.y * 128;
    const int n0 = blockIdx.x * 128;
    unsigned long long acc[4][8];
    gemm_big_core(x, HID, w, 3 * NHEAD * DH, HID, m0, n0, acc);
    float r[8][8];
    unpack_big(acc, r);

    const int tx = threadIdx.x & 15;
    const int ty = threadIdx.x >> 4;
    const int nb   = n0 + (tx << 3);          // thread col base
    const int sel  = nb / (NHEAD * DH);
    const int head = (nb % (NHEAD * DH)) >> 6;
    const int cih  = nb & 63;                  // col within head
    float* dst = (sel == 0) ? g_q : (sel == 1) ? g_k : g_v;

    #pragma unroll
    for (int rr = 0; rr < 8; ++rr) {
        const int m = m0 + (ty << 3) + rr;
        const int b = m >> 10;
        const int tok = m & 1023;
        float* row = dst + (((size_t)(b * NHEAD + head) * NTOK + tok) << 6) + cih;
        *reinterpret_cast<float4*>(row) =
            make_float4(r[rr][0], r[rr][1], r[rr][2], r[rr][3]);
        *reinterpret_cast<float4*>(row + 4) =
            make_float4(r[rr][4], r[rr][5], r[rr][6], r[rr][7]);
    }
}

// ---------------- 2) transpose K ----------------
__global__ __launch_bounds__(256) void k_transpose()
{
    __shared__ float t[32][33];
    const int bh   = blockIdx.z;
    const int tok0 = blockIdx.x * 32;
    const int d0   = blockIdx.y * 32;
    const int x  = threadIdx.x;
    const int y0 = threadIdx.y;
    const float* src = g_k  + ((size_t)bh << 16);
    float*       dst = g_kT + ((size_t)bh << 16);
    #pragma unroll
    for (int yy = 0; yy < 32; yy += 8)
        t[y0 + yy][x] = src[(size_t)(tok0 + y0 + yy) * DH + d0 + x];
    __syncthreads();
    #pragma unroll
    for (int yy = 0; yy < 32; yy += 8)
        dst[(size_t)(d0 + y0 + yy) * NTOK + tok0 + x] = t[x][y0 + yy];
}

// ---------------- 3) rel_h / rel_w tables ----------------
__global__ __launch_bounds__(64) void k_rel(
    const float* __restrict__ rel_pos_h, const float* __restrict__ rel_pos_w)
{
    const int bh  = blockIdx.y;
    const int tok = blockIdx.x;
    __shared__ float qs[64];
    const int t = threadIdx.x;
    qs[t] = g_q[(((size_t)bh << 10) + tok) * DH + t];
    __syncthreads();

    const int qh = tok >> 5;
    const int qw = tok & 31;
    const float* rp;
    float* out;
    int ridx;
    if (t < 32) {
        rp = rel_pos_h; ridx = qh - t + (HDIM - 1);
        out = &g_relh[(((size_t)bh << 10) + tok) * 32 + t];
    } else {
        const int kw = t - 32;
        rp = rel_pos_w; ridx = qw - kw + (WDIM - 1);
        out = &g_relw[(((size_t)bh << 10) + tok) * 32 + kw];
    }
    const float* rr = rp + (size_t)ridx * DH;
    float s = 0.f;
    #pragma unroll
    for (int c = 0; c < 64; ++c) s = fmaf(qs[c], rr[c], s);
    *out = s;
}

// ---------------- 4) logits = scale*Q@K^T + rel_h + rel_w ----------------
__global__ __launch_bounds__(256) void k_logits()
{
    const int bh = blockIdx.z;
    const int m0 = blockIdx.y * 128;
    const int n0 = blockIdx.x * 128;
    const float* A = g_q  + ((size_t)bh << 16);
    const float* B = g_kT + ((size_t)bh << 16);
    unsigned long long acc[4][8];
    gemm_big_core(A, DH, B, NTOK, DH, m0, n0, acc);
    float r[8][8];
    unpack_big(acc, r);

    const int tx = threadIdx.x & 15;
    const int ty = threadIdx.x >> 4;
    const float scale = 0.125f;
    const int col0 = n0 + (tx << 3);
    const int kh   = col0 >> 5;                // constant over the 8 cols
    const int kw0  = col0 & 31;                // 0,8,16,24
    float* outb = g_attn + ((size_t)bh << 20);

    #pragma unroll
    for (int rr = 0; rr < 8; ++rr) {
        const int tok = m0 + (ty << 3) + rr;
        const float bias = g_relh[(((size_t)bh << 10) + tok) * 32 + kh];
        const float* rw = g_relw + (((size_t)bh << 10) + tok) * 32 + kw0;
        float4 w0 = *reinterpret_cast<const float4*>(rw);
        float4 w1 = *reinterpret_cast<const float4*>(rw + 4);
        float4 o0, o1;
        o0.x = fmaf(r[rr][0], scale, bias + w0.x);
        o0.y = fmaf(r[rr][1], scale, bias + w0.y);
        o0.z = fmaf(r[rr][2], scale, bias + w0.z);
        o0.w = fmaf(r[rr][3], scale, bias + w0.w);
        o1.x = fmaf(r[rr][4], scale, bias + w1.x);
        o1.y = fmaf(r[rr][5], scale, bias + w1.y);
        o1.z = fmaf(r[rr][6], scale, bias + w1.z);
        o1.w = fmaf(r[rr][7], scale, bias + w1.w);
        float* dst = &outb[((size_t)tok << 10) + col0];
        *reinterpret_cast<float4*>(dst)     = o0;
        *reinterpret_cast<float4*>(dst + 4) = o1;
    }
}

// ---------------- 5) fused softmax + PV: out = softmax(attn) @ V -> g_o --------
__global__ __launch_bounds__(256) void k_pv()
{
    __shared__ float sM[128];
    __shared__ float sInvL[128];

    const int bh = blockIdx.y;
    const int m0 = blockIdx.x * 128;
    const int tid = threadIdx.x;
    const int warp = tid >> 5, lane = tid & 31;

    // prepass: each warp computes online (max, sum) for 16 rows
    const float* attnb = g_attn + ((size_t)bh << 20);
    for (int rr = 0; rr < 16; ++rr) {
        const int rloc = warp * 16 + rr;
        const float4* p = (const float4*)(attnb + ((size_t)(m0 + rloc) << 10));
        float m = -3.4e38f, l = 0.f;
        #pragma unroll
        for (int i = 0; i < 8; ++i) {
            float4 v = p[lane + i * 32];
            float mx = fmaxf(fmaxf(v.x, v.y), fmaxf(v.z, v.w));
            if (mx > m) { l *= __expf(m - mx); m = mx; }
            l += __expf(v.x - m) + __expf(v.y - m)
               + __expf(v.z - m) + __expf(v.w - m);
        }
        #pragma unroll
        for (int o = 16; o > 0; o >>= 1) {
            float mo = __shfl_xor_sync(0xffffffffu, m, o);
            float lo = __shfl_xor_sync(0xffffffffu, l, o);
            float M2 = fmaxf(m, mo);
            l = l * __expf(m - M2) + lo * __expf(mo - M2);
            m = M2;
        }
        if (lane == 0) { sM[rloc] = m; sInvL[rloc] = 1.0f / l; }
    }
    __syncthreads();

    unsigned long long acc[4][4] = {};
    gemm_pv_core(attnb, NTOK,
                 g_v + ((size_t)bh << 16), DH,
                 NTOK, m0, sM, acc);
    float r[8][4];
    unpack_acc(acc, r);

    const int tx = tid & 15;
    const int ty = tid >> 4;
    const int head = bh % NHEAD;
    const int b    = bh / NHEAD;

    #pragma unroll
    for (int rr = 0; rr < 8; ++rr) {
        const int rloc = (ty << 3) + rr;
        const int tok = m0 + rloc;
        const float inv = sInvL[rloc];
        float4 v4 = make_float4(r[rr][0] * inv, r[rr][1] * inv,
                                r[rr][2] * inv, r[rr][3] * inv);
        *reinterpret_cast<float4*>(
            &g_o[(size_t)(b * NTOK + tok) * HID + head * DH + (tx << 2)]) = v4;
    }
}

// ---------------- 6) final projection ----------------
__global__ __launch_bounds__(256) void k_out(
    const float* __restrict__ w, const float* __restrict__ bias,
    float* __restrict__ out)
{
    const int m0 = blockIdx.y * 128;
    const int n0 = blockIdx.x * 128;
    unsigned long long acc[4][8];
    gemm_big_core(g_o, HID, w, HID, HID, m0, n0, acc);
    float r[8][8];
    unpack_big(acc, r);

    const int tx = threadIdx.x & 15;
    const int ty = threadIdx.x >> 4;
    const int col0 = n0 + (tx << 3);
    float4 bb0 = *reinterpret_cast<const float4*>(&bias[col0]);
    float4 bb1 = *reinterpret_cast<const float4*>(&bias[col0 + 4]);

    #pragma unroll
    for (int rr = 0; rr < 8; ++rr) {
        const int m = m0 + (ty << 3) + rr;
        float* dst = &out[(size_t)m * HID + col0];
        *reinterpret_cast<float4*>(dst) =
            make_float4(r[rr][0] + bb0.x, r[rr][1] + bb0.y,
                        r[rr][2] + bb0.z, r[rr][3] + bb0.w);
        *reinterpret_cast<float4*>(dst + 4) =
            make_float4(r[rr][4] + bb1.x, r[rr][5] + bb1.y,
                        r[rr][6] + bb1.z, r[rr][7] + bb1.w);
    }
}

// ---------------- launcher ----------------
extern "C" void kernel_launch(void* const* d_in, const int* in_sizes, int n_in,
                              void* d_out, int out_size)
{
    const float* x         = (const float*)d_in[0];
    const float* w_qkv     = (const float*)d_in[1];
    const float* w_out     = (const float*)d_in[2];
    const float* b_out     = (const float*)d_in[3];
    const float* rel_pos_h = (const float*)d_in[4];
    const float* rel_pos_w = (const float*)d_in[5];
    float* out = (float*)d_out;

    k_gemm_qkv<<<dim3(18, 32), 256>>>(x, w_qkv);
    k_transpose<<<dim3(32, 2, BH), dim3(32, 8)>>>();
    k_rel<<<dim3(NTOK, BH), 64>>>(rel_pos_h, rel_pos_w);
    k_logits<<<dim3(8, 8, BH), 256>>>();
    k_pv<<<dim3(8, BH), 256>>>();
    k_out<<<dim3(6, 32), 256>>>(w_out, b_out, out);
}

// round 13
// speedup vs baseline: 1.1032x; 1.0083x over previous
#include <cuda_runtime.h>
#include <cstdint>
#include <cstddef>

// Problem constants
#define BATCH   4
#define NHEAD   12
#define DH      64
#define HID     768
#define HDIM    32
#define WDIM    32
#define NTOK    1024
#define BH      48
#define MTOK    4096

// ---------------- scratch (device globals) ----------------
__device__ float g_q   [(size_t)BH * NTOK * DH];
__device__ float g_k   [(size_t)BH * NTOK * DH];
__device__ float g_kT  [(size_t)BH * DH * NTOK];
__device__ float g_v   [(size_t)BH * NTOK * DH];
__device__ float g_relh[(size_t)BH * NTOK * 32];
__device__ float g_relw[(size_t)BH * NTOK * 32];
__device__ float g_attn[(size_t)BH * NTOK * NTOK];
__device__ float g_o   [(size_t)MTOK * HID];

// ---------------- f32x2 packed helpers ----------------
#define FMA2(d, a, b) \
    asm("fma.rn.f32x2 %0, %1, %2, %0;" : "+l"(d) : "l"(a), "l"(b))
#define PACK2(d, x, y) \
    asm("mov.b64 %0, {%1, %2};" : "=l"(d) : "r"(__float_as_uint(x)), "r"(__float_as_uint(y)))
#define UNPACK2(x, y, d) do {                                   \
    unsigned _lo, _hi;                                          \
    asm("mov.b64 {%0, %1}, %2;" : "=r"(_lo), "=r"(_hi) : "l"(d)); \
    x = __uint_as_float(_lo); y = __uint_as_float(_hi); } while (0)

// ================= 128x128x16 big core (8x8 micro) — qkv / out ===============
__device__ __forceinline__ void gemm_big_core(
    const float* __restrict__ A, int lda,
    const float* __restrict__ B, int ldb,
    int K, int m0, int n0, unsigned long long acc[4][8])
{
    __shared__ __align__(16) float As[16][132];
    __shared__ __align__(16) float Bs[16][132];

    const int tid = threadIdx.x;
    const int tx  = tid & 15;
    const int ty  = tid >> 4;

    const int ra  = tid >> 1;
    const int ka  = (tid & 1) << 3;
    const int krb = tid >> 4;
    const int qb  = (tid & 15) << 3;

    const float* pa = A + (size_t)(m0 + ra) * lda + ka;
    const float* pb = B + (size_t)krb * ldb + n0 + qb;

    float4 va0 = *reinterpret_cast<const float4*>(pa);
    float4 va1 = *reinterpret_cast<const float4*>(pa + 4);
    float4 vb0 = *reinterpret_cast<const float4*>(pb);
    float4 vb1 = *reinterpret_cast<const float4*>(pb + 4);

    #pragma unroll
    for (int ip = 0; ip < 4; ++ip)
        #pragma unroll
        for (int j = 0; j < 8; ++j) acc[ip][j] = 0ull;

    for (int k0 = 0; k0 < K; k0 += 16) {
        As[ka + 0][ra] = va0.x; As[ka + 1][ra] = va0.y;
        As[ka + 2][ra] = va0.z; As[ka + 3][ra] = va0.w;
        As[ka + 4][ra] = va1.x; As[ka + 5][ra] = va1.y;
        As[ka + 6][ra] = va1.z; As[ka + 7][ra] = va1.w;
        *reinterpret_cast<float4*>(&Bs[krb][qb])     = vb0;
        *reinterpret_cast<float4*>(&Bs[krb][qb + 4]) = vb1;
        __syncthreads();

        const int kn = k0 + 16;
        if (kn < K) {
            va0 = *reinterpret_cast<const float4*>(pa + kn);
            va1 = *reinterpret_cast<const float4*>(pa + kn + 4);
            vb0 = *reinterpret_cast<const float4*>(pb + (size_t)kn * ldb);
            vb1 = *reinterpret_cast<const float4*>(pb + (size_t)kn * ldb + 4);
        }

        #pragma unroll
        for (int kk = 0; kk < 16; ++kk) {
            const ulonglong2* ap =
                reinterpret_cast<const ulonglong2*>(&As[kk][ty << 3]);
            ulonglong2 aa = ap[0];
            ulonglong2 ab = ap[1];
            unsigned long long apair[4] = {aa.x, aa.y, ab.x, ab.y};
            float4 b0 = *reinterpret_cast<const float4*>(&Bs[kk][tx << 3]);
            float4 b1 = *reinterpret_cast<const float4*>(&Bs[kk][(tx << 3) + 4]);
            float bv[8] = {b0.x, b0.y, b0.z, b0.w, b1.x, b1.y, b1.z, b1.w};
            #pragma unroll
            for (int j = 0; j < 8; ++j) {
                unsigned long long bp;
                PACK2(bp, bv[j], bv[j]);
                #pragma unroll
                for (int ip = 0; ip < 4; ++ip)
                    FMA2(acc[ip][j], apair[ip], bp);
            }
        }
        __syncthreads();
    }
}

__device__ __forceinline__ void unpack_big(
    const unsigned long long acc[4][8], float r[8][8])
{
    #pragma unroll
    for (int ip = 0; ip < 4; ++ip)
        #pragma unroll
        for (int j = 0; j < 8; ++j)
            UNPACK2(r[2 * ip][j], r[2 * ip + 1][j], acc[ip][j]);
}

// ================= 128x64x16 core (8x4 micro) — logits ========================
__device__ __forceinline__ void gemm_s_core(
    const float* __restrict__ A, int lda,
    const float* __restrict__ B, int ldb,
    int K, int m0, int n0, unsigned long long acc[4][4])
{
    __shared__ __align__(16) float As[16][132];
    __shared__ __align__(16) float Bs[16][68];

    const int tid = threadIdx.x;
    const int tx  = tid & 15;
    const int ty  = tid >> 4;

    const int ra  = tid >> 1;
    const int ka  = (tid & 1) << 3;
    const int krb = tid >> 4;
    const int qb  = (tid & 15) << 2;

    const float* pa = A + (size_t)(m0 + ra) * lda + ka;
    const float* pb = B + (size_t)krb * ldb + n0 + qb;

    float4 va0 = *reinterpret_cast<const float4*>(pa);
    float4 va1 = *reinterpret_cast<const float4*>(pa + 4);
    float4 vb  = *reinterpret_cast<const float4*>(pb);

    for (int k0 = 0; k0 < K; k0 += 16) {
        As[ka + 0][ra] = va0.x; As[ka + 1][ra] = va0.y;
        As[ka + 2][ra] = va0.z; As[ka + 3][ra] = va0.w;
        As[ka + 4][ra] = va1.x; As[ka + 5][ra] = va1.y;
        As[ka + 6][ra] = va1.z; As[ka + 7][ra] = va1.w;
        *reinterpret_cast<float4*>(&Bs[krb][qb]) = vb;
        __syncthreads();

        const int kn = k0 + 16;
        if (kn < K) {
            va0 = *reinterpret_cast<const float4*>(pa + kn);
            va1 = *reinterpret_cast<const float4*>(pa + kn + 4);
            vb  = *reinterpret_cast<const float4*>(pb + (size_t)kn * ldb);
        }

        #pragma unroll
        for (int kk = 0; kk < 16; ++kk) {
            const ulonglong2* ap =
                reinterpret_cast<const ulonglong2*>(&As[kk][ty << 3]);
            ulonglong2 aa = ap[0];
            ulonglong2 ab = ap[1];
            unsigned long long apair[4] = {aa.x, aa.y, ab.x, ab.y};
            float4 b4 = *reinterpret_cast<const float4*>(&Bs[kk][tx << 2]);
            unsigned long long bp[4];
            PACK2(bp[0], b4.x, b4.x);
            PACK2(bp[1], b4.y, b4.y);
            PACK2(bp[2], b4.z, b4.z);
            PACK2(bp[3], b4.w, b4.w);
            #pragma unroll
            for (int ip = 0; ip < 4; ++ip)
                #pragma unroll
                for (int j = 0; j < 4; ++j)
                    FMA2(acc[ip][j], apair[ip], bp[j]);
        }
        __syncthreads();
    }
}

// ---------------- PV core (BN=64, 8x4 micro) with exp at A-store --------------
__device__ __forceinline__ void gemm_pv_core(
    const float* __restrict__ A, int lda,
    const float* __restrict__ B, int ldb,
    int K, int m0, const float* __restrict__ sM,
    unsigned long long acc[4][4])
{
    __shared__ __align__(16) float As[16][132];
    __shared__ __align__(16) float Bs[16][68];

    const int tid = threadIdx.x;
    const int tx  = tid & 15;
    const int ty  = tid >> 4;

    const int ra  = tid >> 1;
    const int ka  = (tid & 1) << 3;
    const int krb = tid >> 4;
    const int qb  = (tid & 15) << 2;

    const float* pa = A + (size_t)(m0 + ra) * lda + ka;
    const float* pb = B + (size_t)krb * ldb + qb;
    const float Mr = sM[ra];

    float4 va0 = *reinterpret_cast<const float4*>(pa);
    float4 va1 = *reinterpret_cast<const float4*>(pa + 4);
    float4 vb  = *reinterpret_cast<const float4*>(pb);

    for (int k0 = 0; k0 < K; k0 += 16) {
        As[ka + 0][ra] = __expf(va0.x - Mr);
        As[ka + 1][ra] = __expf(va0.y - Mr);
        As[ka + 2][ra] = __expf(va0.z - Mr);
        As[ka + 3][ra] = __expf(va0.w - Mr);
        As[ka + 4][ra] = __expf(va1.x - Mr);
        As[ka + 5][ra] = __expf(va1.y - Mr);
        As[ka + 6][ra] = __expf(va1.z - Mr);
        As[ka + 7][ra] = __expf(va1.w - Mr);
        *reinterpret_cast<float4*>(&Bs[krb][qb]) = vb;
        __syncthreads();

        const int kn = k0 + 16;
        if (kn < K) {
            va0 = *reinterpret_cast<const float4*>(pa + kn);
            va1 = *reinterpret_cast<const float4*>(pa + kn + 4);
            vb  = *reinterpret_cast<const float4*>(pb + (size_t)kn * ldb);
        }

        #pragma unroll
        for (int kk = 0; kk < 16; ++kk) {
            const ulonglong2* ap =
                reinterpret_cast<const ulonglong2*>(&As[kk][ty << 3]);
            ulonglong2 aa = ap[0];
            ulonglong2 ab = ap[1];
            unsigned long long apair[4] = {aa.x, aa.y, ab.x, ab.y};
            float4 b4 = *reinterpret_cast<const float4*>(&Bs[kk][tx << 2]);
            unsigned long long bp[4];
            PACK2(bp[0], b4.x, b4.x);
            PACK2(bp[1], b4.y, b4.y);
            PACK2(bp[2], b4.z, b4.z);
            PACK2(bp[3], b4.w, b4.w);
            #pragma unroll
            for (int ip = 0; ip < 4; ++ip)
                #pragma unroll
                for (int j = 0; j < 4; ++j)
                    FMA2(acc[ip][j], apair[ip], bp[j]);
        }
        __syncthreads();
    }
}

__device__ __forceinline__ void unpack_acc(
    const unsigned long long acc[4][4], float r[8][4])
{
    #pragma unroll
    for (int ip = 0; ip < 4; ++ip)
        #pragma unroll
        for (int j = 0; j < 4; ++j)
            UNPACK2(r[2 * ip][j], r[2 * ip + 1][j], acc[ip][j]);
}

// ---------------- 1) qkv = x @ w_qkv, scatter to g_q/g_k/g_v ----------------
__global__ __launch_bounds__(256) void k_gemm_qkv(
    const float* __restrict__ x, const float* __restrict__ w)
{
    const int m0 = blockIdx.y * 128;
    const int n0 = blockIdx.x * 128;
    unsigned long long acc[4][8];
    gemm_big_core(x, HID, w, 3 * NHEAD * DH, HID, m0, n0, acc);
    float r[8][8];
    unpack_big(acc, r);

    const int tx = threadIdx.x & 15;
    const int ty = threadIdx.x >> 4;
    const int nb   = n0 + (tx << 3);
    const int sel  = nb / (NHEAD * DH);
    const int head = (nb % (NHEAD * DH)) >> 6;
    const int cih  = nb & 63;
    float* dst = (sel == 0) ? g_q : (sel == 1) ? g_k : g_v;

    #pragma unroll
    for (int rr = 0; rr < 8; ++rr) {
        const int m = m0 + (ty << 3) + rr;
        const int b = m >> 10;
        const int tok = m & 1023;
        float* row = dst + (((size_t)(b * NHEAD + head) * NTOK + tok) << 6) + cih;
        *reinterpret_cast<float4*>(row) =
            make_float4(r[rr][0], r[rr][1], r[rr][2], r[rr][3]);
        *reinterpret_cast<float4*>(row + 4) =
            make_float4(r[rr][4], r[rr][5], r[rr][6], r[rr][7]);
    }
}

// ---------------- 2) transpose K ----------------
__global__ __launch_bounds__(256) void k_transpose()
{
    __shared__ float t[32][33];
    const int bh   = blockIdx.z;
    const int tok0 = blockIdx.x * 32;
    const int d0   = blockIdx.y * 32;
    const int x  = threadIdx.x;
    const int y0 = threadIdx.y;
    const float* src = g_k  + ((size_t)bh << 16);
    float*       dst = g_kT + ((size_t)bh << 16);
    #pragma unroll
    for (int yy = 0; yy < 32; yy += 8)
        t[y0 + yy][x] = src[(size_t)(tok0 + y0 + yy) * DH + d0 + x];
    __syncthreads();
    #pragma unroll
    for (int yy = 0; yy < 32; yy += 8)
        dst[(size_t)(d0 + y0 + yy) * NTOK + tok0 + x] = t[x][y0 + yy];
}

// ---------------- 3) rel_h / rel_w tables ----------------
__global__ __launch_bounds__(64) void k_rel(
    const float* __restrict__ rel_pos_h, const float* __restrict__ rel_pos_w)
{
    const int bh  = blockIdx.y;
    const int tok = blockIdx.x;
    __shared__ float qs[64];
    const int t = threadIdx.x;
    qs[t] = g_q[(((size_t)bh << 10) + tok) * DH + t];
    __syncthreads();

    const int qh = tok >> 5;
    const int qw = tok & 31;
    const float* rp;
    float* out;
    int ridx;
    if (t < 32) {
        rp = rel_pos_h; ridx = qh - t + (HDIM - 1);
        out = &g_relh[(((size_t)bh << 10) + tok) * 32 + t];
    } else {
        const int kw = t - 32;
        rp = rel_pos_w; ridx = qw - kw + (WDIM - 1);
        out = &g_relw[(((size_t)bh << 10) + tok) * 32 + kw];
    }
    const float* rr = rp + (size_t)ridx * DH;
    float s = 0.f;
    #pragma unroll
    for (int c = 0; c < 64; ++c) s = fmaf(qs[c], rr[c], s);
    *out = s;
}

// ---------------- 4) logits = scale*Q@K^T + rel_h + rel_w (8x4 core) -----------
__global__ __launch_bounds__(256) void k_logits()
{
    const int bh = blockIdx.z;
    const int m0 = blockIdx.y * 128;
    const int n0 = blockIdx.x * 64;
    const float* A = g_q  + ((size_t)bh << 16);
    const float* B = g_kT + ((size_t)bh << 16);
    unsigned long long acc[4][4] = {};
    gemm_s_core(A, DH, B, NTOK, DH, m0, n0, acc);
    float r[8][4];
    unpack_acc(acc, r);

    const int tx = threadIdx.x & 15;
    const int ty = threadIdx.x >> 4;
    const float scale = 0.125f;
    const int col0 = n0 + (tx << 2);
    const int kh   = col0 >> 5;
    const int kw0  = col0 & 31;
    float* outb = g_attn + ((size_t)bh << 20);

    #pragma unroll
    for (int rr = 0; rr < 8; ++rr) {
        const int tok = m0 + (ty << 3) + rr;
        const float* rh = g_relh + (((size_t)bh << 10) + tok) * 32;
        const float* rw = g_relw + (((size_t)bh << 10) + tok) * 32;
        const float bias = rh[kh];
        float4 v;
        v.x = fmaf(r[rr][0], scale, bias + rw[kw0 + 0]);
        v.y = fmaf(r[rr][1], scale, bias + rw[kw0 + 1]);
        v.z = fmaf(r[rr][2], scale, bias + rw[kw0 + 2]);
        v.w = fmaf(r[rr][3], scale, bias + rw[kw0 + 3]);
        *reinterpret_cast<float4*>(&outb[((size_t)tok << 10) + col0]) = v;
    }
}

// ---------------- 5) fused softmax + PV ----------------
__global__ __launch_bounds__(256) void k_pv()
{
    __shared__ float sM[128];
    __shared__ float sInvL[128];

    const int bh = blockIdx.y;
    const int m0 = blockIdx.x * 128;
    const int tid = threadIdx.x;
    const int warp = tid >> 5, lane = tid & 31;

    // prepass: per row, load all 8 float4 (MLP=8), then max, then sum of exps
    const float* attnb = g_attn + ((size_t)bh << 20);
    for (int rr = 0; rr < 16; ++rr) {
        const int rloc = warp * 16 + rr;
        const float4* p = (const float4*)(attnb + ((size_t)(m0 + rloc) << 10));
        float4 v[8];
        #pragma unroll
        for (int i = 0; i < 8; ++i) v[i] = p[lane + i * 32];

        float m = -3.4e38f;
        #pragma unroll
        for (int i = 0; i < 8; ++i)
            m = fmaxf(m, fmaxf(fmaxf(v[i].x, v[i].y), fmaxf(v[i].z, v[i].w)));
        #pragma unroll
        for (int o = 16; o > 0; o >>= 1)
            m = fmaxf(m, __shfl_xor_sync(0xffffffffu, m, o));

        float l = 0.f;
        #pragma unroll
        for (int i = 0; i < 8; ++i)
            l += __expf(v[i].x - m) + __expf(v[i].y - m)
               + __expf(v[i].z - m) + __expf(v[i].w - m);
        #pragma unroll
        for (int o = 16; o > 0; o >>= 1)
            l += __shfl_xor_sync(0xffffffffu, l, o);

        if (lane == 0) { sM[rloc] = m; sInvL[rloc] = 1.0f / l; }
    }
    __syncthreads();

    unsigned long long acc[4][4] = {};
    gemm_pv_core(attnb, NTOK,
                 g_v + ((size_t)bh << 16), DH,
                 NTOK, m0, sM, acc);
    float r[8][4];
    unpack_acc(acc, r);

    const int tx = tid & 15;
    const int ty = tid >> 4;
    const int head = bh % NHEAD;
    const int b    = bh / NHEAD;

    #pragma unroll
    for (int rr = 0; rr < 8; ++rr) {
        const int rloc = (ty << 3) + rr;
        const int tok = m0 + rloc;
        const float inv = sInvL[rloc];
        float4 v4 = make_float4(r[rr][0] * inv, r[rr][1] * inv,
                                r[rr][2] * inv, r[rr][3] * inv);
        *reinterpret_cast<float4*>(
            &g_o[(size_t)(b * NTOK + tok) * HID + head * DH + (tx << 2)]) = v4;
    }
}

// ---------------- 6) final projection (big core) ----------------
__global__ __launch_bounds__(256) void k_out(
    const float* __restrict__ w, const float* __restrict__ bias,
    float* __restrict__ out)
{
    const int m0 = blockIdx.y * 128;
    const int n0 = blockIdx.x * 128;
    unsigned long long acc[4][8];
    gemm_big_core(g_o, HID, w, HID, HID, m0, n0, acc);
    float r[8][8];
    unpack_big(acc, r);

    const int tx = threadIdx.x & 15;
    const int ty = threadIdx.x >> 4;
    const int col0 = n0 + (tx << 3);
    float4 bb0 = *reinterpret_cast<const float4*>(&bias[col0]);
    float4 bb1 = *reinterpret_cast<const float4*>(&bias[col0 + 4]);

    #pragma unroll
    for (int rr = 0; rr < 8; ++rr) {
        const int m = m0 + (ty << 3) + rr;
        float* dst = &out[(size_t)m * HID + col0];
        *reinterpret_cast<float4*>(dst) =
            make_float4(r[rr][0] + bb0.x, r[rr][1] + bb0.y,
                        r[rr][2] + bb0.z, r[rr][3] + bb0.w);
        *reinterpret_cast<float4*>(dst + 4) =
            make_float4(r[rr][4] + bb1.x, r[rr][5] + bb1.y,
                        r[rr][6] + bb1.z, r[rr][7] + bb1.w);
    }
}

// ---------------- launcher ----------------
extern "C" void kernel_launch(void* const* d_in, const int* in_sizes, int n_in,
                              void* d_out, int out_size)
{
    const float* x         = (const float*)d_in[0];
    const float* w_qkv     = (const float*)d_in[1];
    const float* w_out     = (const float*)d_in[2];
    const float* b_out     = (const float*)d_in[3];
    const float* rel_pos_h = (const float*)d_in[4];
    const float* rel_pos_w = (const float*)d_in[5];
    float* out = (float*)d_out;

    k_gemm_qkv<<<dim3(18, 32), 256>>>(x, w_qkv);
    k_transpose<<<dim3(32, 2, BH), dim3(32, 8)>>>();
    k_rel<<<dim3(NTOK, BH), 64>>>(rel_pos_h, rel_pos_w);
    k_logits<<<dim3(16, 8, BH), 256>>>();
    k_pv<<<dim3(8, BH), 256>>>();
    k_out<<<dim3(6, 32), 256>>>(w_out, b_out, out);
}